// round 11
// baseline (speedup 1.0000x reference)
#include <cuda_runtime.h>
#include <cuda_bf16.h>

// Problem constants (fixed by the reference: B=4, S=2048, D=2048, K=4)
#define N_ROWS       8192      // B*S
#define N_COLS4      512       // float4 per row (D/4)
#define THREADS      512       // one thread per float4 column
#define N_BLOCKS     2048
#define ROWS_PER_BLK (N_ROWS / N_BLOCKS)  // 4

// Scratch: transposed weights + prefolded coefficients. No allocation allowed
// anywhere; __device__ globals are the sanctioned workaround.
__device__ float4 g_wt[2048];   // g_wt[j*512 + c] = w4[4c + j], j in 0..3
__device__ float  g_coef[24];   // cA[0..3] cB[0..3] cC[0..3] cD cE cF

__device__ __forceinline__ float fast_ex2(float a) {
    float r;
    asm("ex2.approx.ftz.f32 %0, %1;" : "=f"(r) : "f"(a));
    return r;
}

// Pre-pass: coalesced-write transpose of weights (the strided reads happen
// once over 32KB -> negligible), plus coefficient folding on one thread.
__global__ void prep_kernel(const float4* __restrict__ w4,
                            const float*  __restrict__ means,
                            const float*  __restrict__ icov)
{
    const int i = blockIdx.x * blockDim.x + threadIdx.x;   // 0..2047
    g_wt[i] = w4[4 * (i & 511) + (i >> 9)];

    if (i == 0) {
        // Expanded quadratic-form coefficients with -0.5*log2(e) folded in:
        //   log2(pdf_k) = A*x^2 + B*x*y + C*y^2 + D*x + E*y + F
        const float L2E = 1.4426950408889634f;
#pragma unroll
        for (int k = 0; k < 4; k++) {
            const float m0 = means[2 * k + 0];
            const float m1 = means[2 * k + 1];
            const float a  = icov[4 * k + 0];
            const float b  = 0.5f * (icov[4 * k + 1] + icov[4 * k + 2]);
            const float cc = icov[4 * k + 3];
            const float C0 = -0.5f * L2E * a;
            const float C1 = -L2E * b;
            const float C2 = -0.5f * L2E * cc;
            g_coef[0  + k] = C0;
            g_coef[4  + k] = C1;
            g_coef[8  + k] = C2;
            g_coef[12 + k] = -(2.0f * C0 * m0 + C1 * m1);
            g_coef[16 + k] = -(C1 * m0 + 2.0f * C2 * m1);
            g_coef[20 + k] = C0 * m0 * m0 + C1 * m0 * m1 + C2 * m1 * m1;
        }
    }
}

// Occupancy experiment: force 3 blocks/SM (regs capped at 42 -> 48 resident
// warps = 75% occ). A few long-live-range values (v[]/idx[]) spill to local;
// lane-coalesced LDL reloads are cheap next to the +75% warp gain.
__global__ void __launch_bounds__(THREADS, 3)
gmm_act_kernel(const float4* __restrict__ xin,
               float4* __restrict__ out)
{
    const int tid = threadIdx.x;

    // Prefolded coefficients (broadcast loads).
    float cA[4], cB[4], cC[4], cD[4], cE[4], cF[4];
#pragma unroll
    for (int k = 0; k < 4; k++) {
        cA[k] = g_coef[0  + k];
        cB[k] = g_coef[4  + k];
        cC[k] = g_coef[8  + k];
        cD[k] = g_coef[12 + k];
        cE[k] = g_coef[16 + k];
        cF[k] = g_coef[20 + k];
    }

    // Weights for this thread's two d-pairs (d0 = 2*tid, d1 = 2*tid+1),
    // fetched from the transposed buffer: 4 fully-coalesced LDG.128.
    const float4 wa = g_wt[       tid];   // w4[4t+0]: d0 k0c0 k0c1 k1c0 k1c1
    const float4 wb = g_wt[ 512 + tid];   // w4[4t+1]: d0 k2c0 k2c1 k3c0 k3c1
    const float4 wc = g_wt[1024 + tid];   // w4[4t+2]: d1 k0c0 k0c1 k1c0 k1c1
    const float4 wd = g_wt[1536 + tid];   // w4[4t+3]: d1 k2c0 k2c1 k3c0 k3c1
    const float w0c0[4] = {wa.x, wa.z, wb.x, wb.z};
    const float w0c1[4] = {wa.y, wa.w, wb.y, wb.w};
    const float w1c0[4] = {wc.x, wc.z, wd.x, wd.z};
    const float w1c1[4] = {wc.y, wc.w, wd.y, wd.w};

    // Front-batch the 4 row loads (MLP=4). Default caching: x stays
    // L2-resident across graph replays (streaming stores protect it).
    float4 v[ROWS_PER_BLK];
    int    idx[ROWS_PER_BLK];
#pragma unroll
    for (int i = 0; i < ROWS_PER_BLK; i++) {
        idx[i] = (blockIdx.x + i * N_BLOCKS) * N_COLS4 + tid;
        v[i]   = xin[idx[i]];
    }

#pragma unroll
    for (int i = 0; i < ROWS_PER_BLK; i++) {
        const float x0 = v[i].x, y0 = v[i].y;
        const float x1 = v[i].z, y1 = v[i].w;

        float r00 = 0.0f, r01 = 0.0f, r10 = 0.0f, r11 = 0.0f;
#pragma unroll
        for (int k = 0; k < 4; k++) {
            // arg = x*(A*x + (B*y + D)) + ((C*y + E)*y + F), depth 3.
            float t0 = fmaf(cA[k], x0, fmaf(cB[k], y0, cD[k]));
            float t1 = fmaf(cA[k], x1, fmaf(cB[k], y1, cD[k]));
            float u0 = fmaf(fmaf(cC[k], y0, cE[k]), y0, cF[k]);
            float u1 = fmaf(fmaf(cC[k], y1, cE[k]), y1, cF[k]);
            const float p0 = fast_ex2(fmaf(x0, t0, u0));
            const float p1 = fast_ex2(fmaf(x1, t1, u1));
            r00 = fmaf(p0, w0c0[k], r00);
            r01 = fmaf(p0, w0c1[k], r01);
            r10 = fmaf(p1, w1c0[k], r10);
            r11 = fmaf(p1, w1c1[k], r11);
        }

        float4 o;
        o.x = x0 * r00;
        o.y = y0 * r01;
        o.z = x1 * r10;
        o.w = y1 * r11;
        // Streaming store: write-once data must not displace x from L2.
        __stcs(&out[idx[i]], o);
    }
}

extern "C" void kernel_launch(void* const* d_in, const int* in_sizes, int n_in,
                              void* d_out, int out_size)
{
    // Inputs identified by element count: x=16777216, means=8, icov=16, w=8192.
    const float* x     = nullptr;
    const float* means = nullptr;
    const float* icov  = nullptr;
    const float* w     = nullptr;
    for (int i = 0; i < n_in; i++) {
        const int n = in_sizes[i];
        if      (n == 16777216) x     = (const float*)d_in[i];
        else if (n == 8)        means = (const float*)d_in[i];
        else if (n == 16)       icov  = (const float*)d_in[i];
        else if (n == 8192)     w     = (const float*)d_in[i];
    }

    prep_kernel<<<8, 256>>>((const float4*)w, means, icov);
    gmm_act_kernel<<<N_BLOCKS, THREADS>>>((const float4*)x, (float4*)d_out);
}

// round 12
// speedup vs baseline: 1.1429x; 1.1429x over previous
#include <cuda_runtime.h>
#include <cuda_bf16.h>

// Problem constants (fixed by the reference: B=4, S=2048, D=2048, K=4)
#define N_ROWS       8192    // B*S
#define N_COLS4      512     // float4 per row (D/4)
#define TPB          256     // half-row per block
#define N_ROWGROUPS  2048
#define ROWS_PER_BLK 4
#define GRID         (2 * N_ROWGROUPS)   // col-half x row-group

// Scratch (__device__ globals: the sanctioned no-allocation pattern).
__device__ float4 g_wt[2048];     // g_wt[j*512 + c] = w4[4c + j], j in 0..3
__device__ float  g_stage[24];    // staging for coefficients
__constant__ float c_coef[24];    // cA[0..3] cB[..] cC cD cE cF (UR-friendly)

__device__ __forceinline__ float fast_ex2(float a) {
    float r;
    asm("ex2.approx.ftz.f32 %0, %1;" : "=f"(r) : "f"(a));
    return r;
}

// Pre-pass: coalesced-write weight transpose + coefficient folding.
__global__ void prep_kernel(const float4* __restrict__ w4,
                            const float*  __restrict__ means,
                            const float*  __restrict__ icov)
{
    const int i = blockIdx.x * blockDim.x + threadIdx.x;   // 0..2047
    g_wt[i] = w4[4 * (i & 511) + (i >> 9)];

    if (i == 0) {
        // log2(pdf_k) = A*x^2 + B*x*y + C*y^2 + D*x + E*y + F  (-0.5*log2e folded)
        const float L2E = 1.4426950408889634f;
#pragma unroll
        for (int k = 0; k < 4; k++) {
            const float m0 = means[2 * k + 0];
            const float m1 = means[2 * k + 1];
            const float a  = icov[4 * k + 0];
            const float b  = 0.5f * (icov[4 * k + 1] + icov[4 * k + 2]);
            const float cc = icov[4 * k + 3];
            const float C0 = -0.5f * L2E * a;
            const float C1 = -L2E * b;
            const float C2 = -0.5f * L2E * cc;
            g_stage[0  + k] = C0;
            g_stage[4  + k] = C1;
            g_stage[8  + k] = C2;
            g_stage[12 + k] = -(2.0f * C0 * m0 + C1 * m1);
            g_stage[16 + k] = -(C1 * m0 + 2.0f * C2 * m1);
            g_stage[20 + k] = C0 * m0 * m0 + C1 * m0 * m1 + C2 * m1 * m1;
        }
    }
}

__global__ void __launch_bounds__(TPB)
gmm_act_kernel(const float4* __restrict__ xin,
               float4* __restrict__ out)
{
    const int tid = threadIdx.x;
    const int c   = ((blockIdx.x & 1) << 8) + tid;   // float4 column 0..511
    const int rb  = blockIdx.x >> 1;                 // row-group 0..2047

    // Weights for this thread's two d-pairs, from the transposed buffer:
    // 4 fully-coalesced LDG.128 (4 L1 wavefronts each).
    const float4 wa = g_wt[       c];   // d0: k0c0 k0c1 k1c0 k1c1
    const float4 wb = g_wt[ 512 + c];   // d0: k2c0 k2c1 k3c0 k3c1
    const float4 wc = g_wt[1024 + c];   // d1: k0c0 k0c1 k1c0 k1c1
    const float4 wd = g_wt[1536 + c];   // d1: k2c0 k2c1 k3c0 k3c1
    const float w0c0[4] = {wa.x, wa.z, wb.x, wb.z};
    const float w0c1[4] = {wa.y, wa.w, wb.y, wb.w};
    const float w1c0[4] = {wc.x, wc.z, wd.x, wd.z};
    const float w1c1[4] = {wc.y, wc.w, wd.y, wd.w};

    // Front-batch the 4 row loads (MLP=4).
    float4 v[ROWS_PER_BLK];
    int    idx[ROWS_PER_BLK];
#pragma unroll
    for (int i = 0; i < ROWS_PER_BLK; i++) {
        idx[i] = (rb + i * N_ROWGROUPS) * N_COLS4 + c;
        v[i]   = xin[idx[i]];
    }

#pragma unroll
    for (int i = 0; i < ROWS_PER_BLK; i++) {
        const float x0 = v[i].x, y0 = v[i].y;
        const float x1 = v[i].z, y1 = v[i].w;

        float r00 = 0.0f, r01 = 0.0f, r10 = 0.0f, r11 = 0.0f;
#pragma unroll
        for (int k = 0; k < 4; k++) {
            // Coefficients come from the constant bank (uniform datapath,
            // zero vector-register cost).
            const float A = c_coef[0  + k];
            const float B = c_coef[4  + k];
            const float C = c_coef[8  + k];
            const float D = c_coef[12 + k];
            const float E = c_coef[16 + k];
            const float F = c_coef[20 + k];
            // arg = x*(A*x + (B*y + D)) + ((C*y + E)*y + F), depth 3.
            float t0 = fmaf(A, x0, fmaf(B, y0, D));
            float t1 = fmaf(A, x1, fmaf(B, y1, D));
            float u0 = fmaf(fmaf(C, y0, E), y0, F);
            float u1 = fmaf(fmaf(C, y1, E), y1, F);
            const float p0 = fast_ex2(fmaf(x0, t0, u0));
            const float p1 = fast_ex2(fmaf(x1, t1, u1));
            r00 = fmaf(p0, w0c0[k], r00);
            r01 = fmaf(p0, w0c1[k], r01);
            r10 = fmaf(p1, w1c0[k], r10);
            r11 = fmaf(p1, w1c1[k], r11);
        }

        float4 o;
        o.x = x0 * r00;
        o.y = y0 * r01;
        o.z = x1 * r10;
        o.w = y1 * r11;
        // Streaming store: write-once data must not displace x from L2.
        __stcs(&out[idx[i]], o);
    }
}

extern "C" void kernel_launch(void* const* d_in, const int* in_sizes, int n_in,
                              void* d_out, int out_size)
{
    // Inputs identified by element count: x=16777216, means=8, icov=16, w=8192.
    const float* x     = nullptr;
    const float* means = nullptr;
    const float* icov  = nullptr;
    const float* w     = nullptr;
    for (int i = 0; i < n_in; i++) {
        const int n = in_sizes[i];
        if      (n == 16777216) x     = (const float*)d_in[i];
        else if (n == 8)        means = (const float*)d_in[i];
        else if (n == 16)       icov  = (const float*)d_in[i];
        else if (n == 8192)     w     = (const float*)d_in[i];
    }

    prep_kernel<<<8, 256>>>((const float4*)w, means, icov);

    // Move folded coefficients into the constant bank (async D2D copy:
    // graph-capturable, no allocation).
    void* stage_ptr = nullptr;
    cudaGetSymbolAddress(&stage_ptr, g_stage);
    cudaMemcpyToSymbolAsync(c_coef, stage_ptr, 24 * sizeof(float), 0,
                            cudaMemcpyDeviceToDevice, 0);

    gmm_act_kernel<<<GRID, TPB>>>((const float4*)x, (float4*)d_out);
}